// round 1
// baseline (speedup 1.0000x reference)
#include <cuda_runtime.h>
#include <cstdint>
#include <cstddef>

#define M_TOK  (12 * 1024)     // 12288 tokens
#define DMODEL 1024
#define NHEAD  16
#define DHEAD  64

// ---------------- scratch (device globals; no allocations) ----------------
__device__ float g_q  [M_TOK * DMODEL];
__device__ float g_k  [M_TOK * DMODEL];
__device__ float g_v  [M_TOK * DMODEL];
__device__ float g_qm [M_TOK * DMODEL];
__device__ float g_km [M_TOK * DMODEL];
__device__ float g_vm [M_TOK * DMODEL];
__device__ float g_am [M_TOK * DMODEL];   // main attention output  [m][h*64+d]
__device__ float g_amv[M_TOK * DMODEL];   // combined MV attention output

// ---------------- packed fp32x2 FMA (Blackwell double-rate fp32) ----------
__device__ __forceinline__ void fma2(float2 &d, float2 a, float2 b) {
    unsigned long long dd = *reinterpret_cast<unsigned long long*>(&d);
    unsigned long long aa = *reinterpret_cast<unsigned long long*>(&a);
    unsigned long long bb = *reinterpret_cast<unsigned long long*>(&b);
    asm("fma.rn.f32x2 %0, %1, %2, %0;" : "+l"(dd) : "l"(aa), "l"(bb));
    *reinterpret_cast<unsigned long long*>(&d) = dd;
}

// =====================================================================
// GEMM: C[m][n] = sum_k A[m][k] * W[n][k]   (A: 12288x1024, W: 1024x1024)
// 128x128 tile, BK=16, 256 threads, 8x8 micro-tile with f32x2.
// =====================================================================
__global__ __launch_bounds__(256) void gemm_proj(const float* __restrict__ A,
                                                 const float* __restrict__ W,
                                                 int out_sel)
{
    __shared__ float As[16][132];
    __shared__ float Ws[16][132];

    float* outp;
    switch (out_sel) {
        case 0: outp = g_q;  break;
        case 1: outp = g_k;  break;
        case 2: outp = g_v;  break;
        case 3: outp = g_qm; break;
        case 4: outp = g_km; break;
        default: outp = g_vm; break;
    }

    const int tid = threadIdx.x;
    const int tx  = tid & 15;
    const int ty  = tid >> 4;
    const int m0  = blockIdx.y * 128;
    const int n0  = blockIdx.x * 128;

    float2 acc[8][4];
#pragma unroll
    for (int i = 0; i < 8; i++)
#pragma unroll
        for (int j = 0; j < 4; j++) acc[i][j] = make_float2(0.f, 0.f);

    const float* Ap = A + (size_t)m0 * DMODEL;
    const float* Wp = W + (size_t)n0 * DMODEL;

    for (int k0 = 0; k0 < DMODEL; k0 += 16) {
        __syncthreads();
#pragma unroll
        for (int i = 0; i < 2; i++) {
            int idx = tid + i * 256;
            int row = idx >> 2, kq = idx & 3;
            float4 av = *(const float4*)(Ap + (size_t)row * DMODEL + k0 + kq * 4);
            As[kq*4+0][row] = av.x; As[kq*4+1][row] = av.y;
            As[kq*4+2][row] = av.z; As[kq*4+3][row] = av.w;
            float4 wv = *(const float4*)(Wp + (size_t)row * DMODEL + k0 + kq * 4);
            Ws[kq*4+0][row] = wv.x; Ws[kq*4+1][row] = wv.y;
            Ws[kq*4+2][row] = wv.z; Ws[kq*4+3][row] = wv.w;
        }
        __syncthreads();
#pragma unroll
        for (int k = 0; k < 16; k++) {
            float2 b[4];
#pragma unroll
            for (int j = 0; j < 4; j++) b[j] = *(const float2*)&Ws[k][tx*8 + j*2];
#pragma unroll
            for (int i = 0; i < 8; i++) {
                float a = As[k][ty*8 + i];
                float2 ap = make_float2(a, a);
#pragma unroll
                for (int j = 0; j < 4; j++) fma2(acc[i][j], ap, b[j]);
            }
        }
    }

#pragma unroll
    for (int i = 0; i < 8; i++) {
        float* cp = outp + (size_t)(m0 + ty*8 + i) * DMODEL + n0 + tx*8;
        *(float4*)cp       = make_float4(acc[i][0].x, acc[i][0].y, acc[i][1].x, acc[i][1].y);
        *(float4*)(cp + 4) = make_float4(acc[i][2].x, acc[i][2].y, acc[i][3].x, acc[i][3].y);
    }
}

// =====================================================================
// Fused output GEMM: C = g_am@Wo^T + g_amv@Wo_mv^T + bo + bo_mv + X
// =====================================================================
__global__ __launch_bounds__(256) void gemm_out(const float* __restrict__ Wo,
                                                const float* __restrict__ bo,
                                                const float* __restrict__ Wom,
                                                const float* __restrict__ bom,
                                                const float* __restrict__ X,
                                                float* __restrict__ C)
{
    __shared__ float As[16][132];
    __shared__ float Ws[16][132];

    const int tid = threadIdx.x;
    const int tx  = tid & 15;
    const int ty  = tid >> 4;
    const int m0  = blockIdx.y * 128;
    const int n0  = blockIdx.x * 128;

    float2 acc[8][4];
#pragma unroll
    for (int i = 0; i < 8; i++)
#pragma unroll
        for (int j = 0; j < 4; j++) acc[i][j] = make_float2(0.f, 0.f);

#pragma unroll 1
    for (int pass = 0; pass < 2; pass++) {
        const float* Ap = (pass ? g_amv : g_am) + (size_t)m0 * DMODEL;
        const float* Wp = (pass ? Wom : Wo)     + (size_t)n0 * DMODEL;
        for (int k0 = 0; k0 < DMODEL; k0 += 16) {
            __syncthreads();
#pragma unroll
            for (int i = 0; i < 2; i++) {
                int idx = tid + i * 256;
                int row = idx >> 2, kq = idx & 3;
                float4 av = *(const float4*)(Ap + (size_t)row * DMODEL + k0 + kq * 4);
                As[kq*4+0][row] = av.x; As[kq*4+1][row] = av.y;
                As[kq*4+2][row] = av.z; As[kq*4+3][row] = av.w;
                float4 wv = *(const float4*)(Wp + (size_t)row * DMODEL + k0 + kq * 4);
                Ws[kq*4+0][row] = wv.x; Ws[kq*4+1][row] = wv.y;
                Ws[kq*4+2][row] = wv.z; Ws[kq*4+3][row] = wv.w;
            }
            __syncthreads();
#pragma unroll
            for (int k = 0; k < 16; k++) {
                float2 b[4];
#pragma unroll
                for (int j = 0; j < 4; j++) b[j] = *(const float2*)&Ws[k][tx*8 + j*2];
#pragma unroll
                for (int i = 0; i < 8; i++) {
                    float a = As[k][ty*8 + i];
                    float2 ap = make_float2(a, a);
#pragma unroll
                    for (int j = 0; j < 4; j++) fma2(acc[i][j], ap, b[j]);
                }
            }
        }
    }

    const int nbase = n0 + tx * 8;
    float4 ba0 = *(const float4*)(bo  + nbase);
    float4 ba1 = *(const float4*)(bo  + nbase + 4);
    float4 bb0 = *(const float4*)(bom + nbase);
    float4 bb1 = *(const float4*)(bom + nbase + 4);
    ba0.x += bb0.x; ba0.y += bb0.y; ba0.z += bb0.z; ba0.w += bb0.w;
    ba1.x += bb1.x; ba1.y += bb1.y; ba1.z += bb1.z; ba1.w += bb1.w;

#pragma unroll
    for (int i = 0; i < 8; i++) {
        size_t roff = (size_t)(m0 + ty*8 + i) * DMODEL + nbase;
        float4 x0 = *(const float4*)(X + roff);
        float4 x1 = *(const float4*)(X + roff + 4);
        float4 r0 = make_float4(acc[i][0].x + ba0.x + x0.x,
                                acc[i][0].y + ba0.y + x0.y,
                                acc[i][1].x + ba0.z + x0.z,
                                acc[i][1].y + ba0.w + x0.w);
        float4 r1 = make_float4(acc[i][2].x + ba1.x + x1.x,
                                acc[i][2].y + ba1.y + x1.y,
                                acc[i][3].x + ba1.z + x1.z,
                                acc[i][3].y + ba1.w + x1.w);
        *(float4*)(C + roff)     = r0;
        *(float4*)(C + roff + 4) = r1;
    }
}

// =====================================================================
// Attention. mode 0: main (L=1024), mode 1: row MV (L=128), mode 2: col MV.
// Token layout for all tensors: [global_token][h*64 + d].
// =====================================================================
__device__ __forceinline__ int tok_idx(int mode, int bat, int pos)
{
    if (mode == 0) return bat * 1024 + pos;
    int bbi, ih, iw, view;
    if (mode == 1) {                       // row: batch=(bbi,ih), seq=(view,iw)
        bbi = bat >> 5; ih = bat & 31;
        view = pos >> 5; iw = pos & 31;
    } else {                               // col: batch=(bbi,iw), seq=(ci,ih)
        bbi = bat >> 5; iw = bat & 31;
        int ci = pos >> 5; ih = pos & 31;
        view = (ci == 0) ? 0 : (ci == 1) ? 2 : (ci == 2) ? 4 : 5;
    }
    return (bbi * 6 + view) * 1024 + ih * 32 + iw;
}

#define QS_STR 66
#define KS_STR 66
#define PS_STR 66
#define VS_STR 72
#define ATTN_SMEM_FLOATS (64*QS_STR + 64*KS_STR + 64*PS_STR + 64*VS_STR)
#define ATTN_SMEM_BYTES  (ATTN_SMEM_FLOATS * 4)

__global__ __launch_bounds__(256) void attn_kernel(int mode)
{
    extern __shared__ float sm[];
    float* Qs = sm;                      // [d][q], stride 66
    float* Ks = Qs + 64 * QS_STR;        // [d][k], stride 66
    float* Ps = Ks + 64 * KS_STR;        // [k][q], stride 66
    float* Vs = Ps + 64 * PS_STR;        // [k][d], stride 72

    const float* Qg; const float* Kg; const float* Vg; float* Og;
    if (mode == 0) { Qg = g_q;  Kg = g_k;  Vg = g_v;  Og = g_am;  }
    else           { Qg = g_qm; Kg = g_km; Vg = g_vm; Og = g_amv; }

    const int L   = (mode == 0) ? 1024 : 128;
    const int tid = threadIdx.x;
    const int tx  = tid & 15;
    const int ty  = tid >> 4;
    const int h   = blockIdx.y;
    const int bat = blockIdx.z;
    const int q0  = blockIdx.x * 64;

    // ---- load Q tile (scaled by 1/sqrt(64)), transposed to [d][q] ----
    {
        const float sc = 0.125f;
#pragma unroll
        for (int i = 0; i < 4; i++) {
            int idx = tid + i * 256;
            int tkn = idx >> 4, d4 = idx & 15;
            int m = tok_idx(mode, bat, q0 + tkn);
            float4 qv = *(const float4*)(Qg + (size_t)m * DMODEL + h * DHEAD + d4 * 4);
            Qs[(d4*4+0)*QS_STR + tkn] = qv.x * sc;
            Qs[(d4*4+1)*QS_STR + tkn] = qv.y * sc;
            Qs[(d4*4+2)*QS_STR + tkn] = qv.z * sc;
            Qs[(d4*4+3)*QS_STR + tkn] = qv.w * sc;
        }
    }

    float  mI[4], lI[4];
    float2 acc[4][2];
#pragma unroll
    for (int qi = 0; qi < 4; qi++) {
        mI[qi] = -1e30f; lI[qi] = 0.f;
        acc[qi][0] = make_float2(0.f, 0.f);
        acc[qi][1] = make_float2(0.f, 0.f);
    }

    for (int kt = 0; kt < L; kt += 64) {
        __syncthreads();
        // ---- load K tile ([d][k]) and V tile ([k][d]) ----
#pragma unroll
        for (int i = 0; i < 4; i++) {
            int idx = tid + i * 256;
            int tkn = idx >> 4, d4 = idx & 15;
            int m = tok_idx(mode, bat, kt + tkn);
            const float* base = Kg + (size_t)m * DMODEL + h * DHEAD + d4 * 4;
            float4 kv = *(const float4*)base;
            Ks[(d4*4+0)*KS_STR + tkn] = kv.x;
            Ks[(d4*4+1)*KS_STR + tkn] = kv.y;
            Ks[(d4*4+2)*KS_STR + tkn] = kv.z;
            Ks[(d4*4+3)*KS_STR + tkn] = kv.w;
            float4 vv = *(const float4*)(Vg + (size_t)m * DMODEL + h * DHEAD + d4 * 4);
            *(float4*)&Vs[tkn * VS_STR + d4 * 4] = vv;
        }
        __syncthreads();

        // ---- scores S = (Q*scale) . K^T  -> s2[qi][pair] ----
        float2 s2[4][2];
#pragma unroll
        for (int qi = 0; qi < 4; qi++) { s2[qi][0] = make_float2(0.f, 0.f); s2[qi][1] = make_float2(0.f, 0.f); }
#pragma unroll
        for (int d = 0; d < 64; d++) {
            float2 b0 = *(const float2*)&Ks[d * KS_STR + tx * 4];
            float2 b1 = *(const float2*)&Ks[d * KS_STR + tx * 4 + 2];
#pragma unroll
            for (int qi = 0; qi < 4; qi++) {
                float a = Qs[d * QS_STR + ty * 4 + qi];
                float2 ap = make_float2(a, a);
                fma2(s2[qi][0], ap, b0);
                fma2(s2[qi][1], ap, b1);
            }
        }

        // ---- online softmax update (row-reduce over the 16 tx lanes) ----
#pragma unroll
        for (int qi = 0; qi < 4; qi++) {
            float tm = fmaxf(fmaxf(s2[qi][0].x, s2[qi][0].y), fmaxf(s2[qi][1].x, s2[qi][1].y));
#pragma unroll
            for (int o = 8; o >= 1; o >>= 1) tm = fmaxf(tm, __shfl_xor_sync(0xffffffffu, tm, o));
            float mn = fmaxf(mI[qi], tm);
            float alpha = __expf(mI[qi] - mn);
            float p0 = __expf(s2[qi][0].x - mn);
            float p1 = __expf(s2[qi][0].y - mn);
            float p2 = __expf(s2[qi][1].x - mn);
            float p3 = __expf(s2[qi][1].y - mn);
            float ts = (p0 + p1) + (p2 + p3);
#pragma unroll
            for (int o = 8; o >= 1; o >>= 1) ts += __shfl_xor_sync(0xffffffffu, ts, o);
            lI[qi] = lI[qi] * alpha + ts;
            mI[qi] = mn;
            acc[qi][0].x *= alpha; acc[qi][0].y *= alpha;
            acc[qi][1].x *= alpha; acc[qi][1].y *= alpha;
            Ps[(tx*4+0)*PS_STR + ty*4 + qi] = p0;
            Ps[(tx*4+1)*PS_STR + ty*4 + qi] = p1;
            Ps[(tx*4+2)*PS_STR + ty*4 + qi] = p2;
            Ps[(tx*4+3)*PS_STR + ty*4 + qi] = p3;
        }
        __syncthreads();

        // ---- acc += P @ V ----
#pragma unroll
        for (int k2 = 0; k2 < 64; k2++) {
            float2 v0 = *(const float2*)&Vs[k2 * VS_STR + tx * 4];
            float2 v1 = *(const float2*)&Vs[k2 * VS_STR + tx * 4 + 2];
#pragma unroll
            for (int qi = 0; qi < 4; qi++) {
                float a = Ps[k2 * PS_STR + ty * 4 + qi];
                float2 ap = make_float2(a, a);
                fma2(acc[qi][0], ap, v0);
                fma2(acc[qi][1], ap, v1);
            }
        }
    }

    // ---- epilogue: normalize + view combination ----
#pragma unroll
    for (int qi = 0; qi < 4; qi++) {
        int pos = q0 + ty * 4 + qi;
        int m = tok_idx(mode, bat, pos);
        float inv = 1.f / lI[qi];
        float4 r = make_float4(acc[qi][0].x * inv, acc[qi][0].y * inv,
                               acc[qi][1].x * inv, acc[qi][1].y * inv);
        float* op = Og + (size_t)m * DMODEL + h * DHEAD + tx * 4;
        if (mode == 0) {
            *(float4*)op = r;
        } else if (mode == 1) {
            int view = pos >> 5;                      // views 0..3
            float w = (view == 0 || view == 2) ? 0.5f : 1.0f;
            r.x *= w; r.y *= w; r.z *= w; r.w *= w;
            *(float4*)op = r;
        } else {
            int ci = pos >> 5;                        // ci 0,1 -> views 0,2 (add 0.5x)
            if (ci < 2) {
                float4 prev = *(float4*)op;
                r.x = prev.x + 0.5f * r.x; r.y = prev.y + 0.5f * r.y;
                r.z = prev.z + 0.5f * r.z; r.w = prev.w + 0.5f * r.w;
            }
            *(float4*)op = r;                         // ci 2,3 -> views 4,5 (store)
        }
    }
}

// =====================================================================
extern "C" void kernel_launch(void* const* d_in, const int* in_sizes, int n_in,
                              void* d_out, int out_size)
{
    const float* x   = (const float*)d_in[0];
    const float* Wq  = (const float*)d_in[1];
    const float* Wk  = (const float*)d_in[2];
    const float* Wv  = (const float*)d_in[3];
    const float* Wo  = (const float*)d_in[4];
    const float* bo  = (const float*)d_in[5];
    const float* Wqm = (const float*)d_in[6];
    const float* Wkm = (const float*)d_in[7];
    const float* Wvm = (const float*)d_in[8];
    const float* Wom = (const float*)d_in[9];
    const float* bom = (const float*)d_in[10];
    float* out = (float*)d_out;

    static bool attr_set = false;
    if (!attr_set) {
        cudaFuncSetAttribute(attn_kernel, cudaFuncAttributeMaxDynamicSharedMemorySize,
                             ATTN_SMEM_BYTES);
        attr_set = true;
    }

    dim3 gg(8, 96), bt(256);
    gemm_proj<<<gg, bt>>>(x, Wq,  0);
    gemm_proj<<<gg, bt>>>(x, Wk,  1);
    gemm_proj<<<gg, bt>>>(x, Wv,  2);
    gemm_proj<<<gg, bt>>>(x, Wqm, 3);
    gemm_proj<<<gg, bt>>>(x, Wkm, 4);
    gemm_proj<<<gg, bt>>>(x, Wvm, 5);

    attn_kernel<<<dim3(16, 16, 12), 256, ATTN_SMEM_BYTES>>>(0);  // main
    attn_kernel<<<dim3(2, 16, 64),  256, ATTN_SMEM_BYTES>>>(1);  // row MV
    attn_kernel<<<dim3(2, 16, 64),  256, ATTN_SMEM_BYTES>>>(2);  // col MV

    gemm_out<<<gg, bt>>>(Wo, bo, Wom, bom, x, out);
}

// round 4
// speedup vs baseline: 2.6735x; 2.6735x over previous
#include <cuda_runtime.h>
#include <cstdint>
#include <cstddef>

#define M_TOK  (12 * 1024)     // 12288 tokens
#define DMODEL 1024
#define NHEAD  16
#define DHEAD  64

// ---------------- scratch (device globals; no allocations) ----------------
__device__ float g_q  [M_TOK * DMODEL];
__device__ float g_k  [M_TOK * DMODEL];
__device__ float g_v  [M_TOK * DMODEL];
__device__ float g_qm [M_TOK * DMODEL];
__device__ float g_km [M_TOK * DMODEL];
__device__ float g_vm [M_TOK * DMODEL];
__device__ float g_am [M_TOK * DMODEL];   // main attention output  [m][h*64+d]
__device__ float g_amv[M_TOK * DMODEL];   // combined MV attention output

// ---------------- TF32 helpers ----------------
__device__ __forceinline__ uint32_t to_tf32(float x) {
    uint32_t r;
    asm("cvt.rna.tf32.f32 %0, %1;" : "=r"(r) : "f"(x));
    return r;
}

__device__ __forceinline__ void mma_tf32(float c[4], const uint32_t a[4], const uint32_t b[2]) {
    asm("mma.sync.aligned.m16n8k8.row.col.f32.tf32.tf32.f32 "
        "{%0,%1,%2,%3},{%4,%5,%6,%7},{%8,%9},{%0,%1,%2,%3};"
        : "+f"(c[0]), "+f"(c[1]), "+f"(c[2]), "+f"(c[3])
        : "r"(a[0]), "r"(a[1]), "r"(a[2]), "r"(a[3]), "r"(b[0]), "r"(b[1]));
}

// =====================================================================
// TF32 tensor-core GEMM: C[m][n] = sum_k A[m][k] * W[n][k]
// 128x128 CTA tile, BK=16, 256 threads (8 warps, 4x2), warp tile 32x64.
// =====================================================================
#define SM_STR 20

struct FragC { float c[2][8][4]; };

__device__ __forceinline__ void gemm_mainloop_pass(
    const float* __restrict__ Ap,   // A + m0*DMODEL
    const float* __restrict__ Wp,   // W + n0*DMODEL
    uint32_t* As, uint32_t* Bs,
    FragC& F)
{
    const int tid  = threadIdx.x;
    const int lane = tid & 31;
    const int wid  = tid >> 5;
    const int gid  = lane >> 2;
    const int tig  = lane & 3;
    const int wm   = (wid & 3) * 32;
    const int wn   = (wid >> 2) * 64;

    const int lrow = tid >> 2;        // 0..63
    const int lcol = (tid & 3) * 4;   // 0,4,8,12

    float4 pa[2], pb[2];

    // prologue: prefetch tile k0=0
#pragma unroll
    for (int p = 0; p < 2; p++) {
        pa[p] = *(const float4*)(Ap + (size_t)(lrow + p * 64) * DMODEL + lcol);
        pb[p] = *(const float4*)(Wp + (size_t)(lrow + p * 64) * DMODEL + lcol);
    }
    __syncthreads();   // smem free (previous pass done)
#pragma unroll
    for (int p = 0; p < 2; p++) {
        int r = lrow + p * 64;
        uint4 ua = make_uint4(to_tf32(pa[p].x), to_tf32(pa[p].y), to_tf32(pa[p].z), to_tf32(pa[p].w));
        uint4 ub = make_uint4(to_tf32(pb[p].x), to_tf32(pb[p].y), to_tf32(pb[p].z), to_tf32(pb[p].w));
        *(uint4*)&As[r * SM_STR + lcol] = ua;
        *(uint4*)&Bs[r * SM_STR + lcol] = ub;
    }
    __syncthreads();

    for (int k0 = 0; k0 < DMODEL; k0 += 16) {
        const bool more = (k0 + 16) < DMODEL;
        if (more) {
#pragma unroll
            for (int p = 0; p < 2; p++) {
                pa[p] = *(const float4*)(Ap + (size_t)(lrow + p * 64) * DMODEL + k0 + 16 + lcol);
                pb[p] = *(const float4*)(Wp + (size_t)(lrow + p * 64) * DMODEL + k0 + 16 + lcol);
            }
        }
#pragma unroll
        for (int ks = 0; ks < 2; ks++) {
            const int kk = ks * 8;
            uint32_t af[2][4];
#pragma unroll
            for (int mt = 0; mt < 2; mt++) {
                int mr = wm + mt * 16;
                af[mt][0] = As[(mr + gid) * SM_STR + kk + tig];
                af[mt][1] = As[(mr + gid + 8) * SM_STR + kk + tig];
                af[mt][2] = As[(mr + gid) * SM_STR + kk + tig + 4];
                af[mt][3] = As[(mr + gid + 8) * SM_STR + kk + tig + 4];
            }
#pragma unroll
            for (int nt = 0; nt < 8; nt++) {
                uint32_t bf[2];
                bf[0] = Bs[(wn + nt * 8 + gid) * SM_STR + kk + tig];
                bf[1] = Bs[(wn + nt * 8 + gid) * SM_STR + kk + tig + 4];
                mma_tf32(F.c[0][nt], af[0], bf);
                mma_tf32(F.c[1][nt], af[1], bf);
            }
        }
        if (more) {
            __syncthreads();
#pragma unroll
            for (int p = 0; p < 2; p++) {
                int r = lrow + p * 64;
                uint4 ua = make_uint4(to_tf32(pa[p].x), to_tf32(pa[p].y), to_tf32(pa[p].z), to_tf32(pa[p].w));
                uint4 ub = make_uint4(to_tf32(pb[p].x), to_tf32(pb[p].y), to_tf32(pb[p].z), to_tf32(pb[p].w));
                *(uint4*)&As[r * SM_STR + lcol] = ua;
                *(uint4*)&Bs[r * SM_STR + lcol] = ub;
            }
            __syncthreads();
        }
    }
}

// ---- 6-way fused projection GEMM: z selects (W, out) pair ----
__global__ __launch_bounds__(256) void gemm_proj_tc(
    const float* __restrict__ A,
    const float* __restrict__ Wq,  const float* __restrict__ Wk,  const float* __restrict__ Wv,
    const float* __restrict__ Wqm, const float* __restrict__ Wkm, const float* __restrict__ Wvm)
{
    __shared__ uint32_t As[128 * SM_STR];
    __shared__ uint32_t Bs[128 * SM_STR];

    const float* W; float* outp;
    switch (blockIdx.z) {
        case 0: W = Wq;  outp = g_q;  break;
        case 1: W = Wk;  outp = g_k;  break;
        case 2: W = Wv;  outp = g_v;  break;
        case 3: W = Wqm; outp = g_qm; break;
        case 4: W = Wkm; outp = g_km; break;
        default: W = Wvm; outp = g_vm; break;
    }

    const int m0 = blockIdx.y * 128;
    const int n0 = blockIdx.x * 128;

    FragC F;
#pragma unroll
    for (int mt = 0; mt < 2; mt++)
#pragma unroll
        for (int nt = 0; nt < 8; nt++)
#pragma unroll
            for (int i = 0; i < 4; i++) F.c[mt][nt][i] = 0.f;

    gemm_mainloop_pass(A + (size_t)m0 * DMODEL, W + (size_t)n0 * DMODEL, As, Bs, F);

    const int lane = threadIdx.x & 31;
    const int wid  = threadIdx.x >> 5;
    const int gid  = lane >> 2;
    const int tig  = lane & 3;
    const int wm   = (wid & 3) * 32;
    const int wn   = (wid >> 2) * 64;

#pragma unroll
    for (int mt = 0; mt < 2; mt++) {
        int row = m0 + wm + mt * 16 + gid;
#pragma unroll
        for (int nt = 0; nt < 8; nt++) {
            int col = n0 + wn + nt * 8 + tig * 2;
            *(float2*)(outp + (size_t)row * DMODEL + col)       = make_float2(F.c[mt][nt][0], F.c[mt][nt][1]);
            *(float2*)(outp + (size_t)(row + 8) * DMODEL + col) = make_float2(F.c[mt][nt][2], F.c[mt][nt][3]);
        }
    }
}

// ---- fused output GEMM: C = g_am@Wo^T + g_amv@Wo_mv^T + bo + bo_mv + X ----
__global__ __launch_bounds__(256) void gemm_out_tc(
    const float* __restrict__ Wo,  const float* __restrict__ bo,
    const float* __restrict__ Wom, const float* __restrict__ bom,
    const float* __restrict__ X,   float* __restrict__ C)
{
    __shared__ uint32_t As[128 * SM_STR];
    __shared__ uint32_t Bs[128 * SM_STR];

    const int m0 = blockIdx.y * 128;
    const int n0 = blockIdx.x * 128;

    FragC F;
#pragma unroll
    for (int mt = 0; mt < 2; mt++)
#pragma unroll
        for (int nt = 0; nt < 8; nt++)
#pragma unroll
            for (int i = 0; i < 4; i++) F.c[mt][nt][i] = 0.f;

    gemm_mainloop_pass(g_am  + (size_t)m0 * DMODEL, Wo  + (size_t)n0 * DMODEL, As, Bs, F);
    gemm_mainloop_pass(g_amv + (size_t)m0 * DMODEL, Wom + (size_t)n0 * DMODEL, As, Bs, F);

    const int lane = threadIdx.x & 31;
    const int wid  = threadIdx.x >> 5;
    const int gid  = lane >> 2;
    const int tig  = lane & 3;
    const int wm   = (wid & 3) * 32;
    const int wn   = (wid >> 2) * 64;

#pragma unroll
    for (int mt = 0; mt < 2; mt++) {
        int row = m0 + wm + mt * 16 + gid;
#pragma unroll
        for (int nt = 0; nt < 8; nt++) {
            int col = n0 + wn + nt * 8 + tig * 2;
            float2 bsum = make_float2(bo[col] + bom[col], bo[col + 1] + bom[col + 1]);
            {
                float2 xv = *(const float2*)(X + (size_t)row * DMODEL + col);
                *(float2*)(C + (size_t)row * DMODEL + col) =
                    make_float2(F.c[mt][nt][0] + bsum.x + xv.x, F.c[mt][nt][1] + bsum.y + xv.y);
            }
            {
                float2 xv = *(const float2*)(X + (size_t)(row + 8) * DMODEL + col);
                *(float2*)(C + (size_t)(row + 8) * DMODEL + col) =
                    make_float2(F.c[mt][nt][2] + bsum.x + xv.x, F.c[mt][nt][3] + bsum.y + xv.y);
            }
        }
    }
}

// =====================================================================
// Tensor-core flash attention. mode 0: main (L=1024), 1: row MV, 2: col MV.
// 128 threads = 4 warps. BQ = BK = 64, Dh = 64.
// Warp w owns q rows [w*16, w*16+16). Q A-fragments live in registers.
// K smem: [tok][d] tf32; V smem transposed: [d][tok] tf32; P smem: [q][tok] tf32.
// =====================================================================
__device__ __forceinline__ int tok_idx(int mode, int bat, int pos)
{
    if (mode == 0) return bat * 1024 + pos;
    int bbi, ih, iw, view;
    if (mode == 1) {                       // row: batch=(bbi,ih), seq=(view,iw)
        bbi = bat >> 5; ih = bat & 31;
        view = pos >> 5; iw = pos & 31;
    } else {                               // col: batch=(bbi,iw), seq=(ci,ih)
        bbi = bat >> 5; iw = bat & 31;
        int ci = pos >> 5; ih = pos & 31;
        view = (ci == 0) ? 0 : (ci == 1) ? 2 : (ci == 2) ? 4 : 5;
    }
    return (bbi * 6 + view) * 1024 + ih * 32 + iw;
}

#define AT_STR 68                          // 68 mod 32 = 4 -> frag reads conflict-free
#define AT_SMEM_BYTES (3 * 64 * AT_STR * 4)

__global__ __launch_bounds__(128) void attn_tc(int mode)
{
    extern __shared__ uint32_t sm[];
    uint32_t* Ks = sm;                     // [tok][d]   tf32
    uint32_t* Vt = sm + 64 * AT_STR;       // [d][tok]   tf32
    uint32_t* Ps = sm + 2 * 64 * AT_STR;   // Q floats, then P tf32, [q][*]
    float*    Pf = (float*)Ps;

    const float* Qg; const float* Kg; const float* Vg; float* Og;
    if (mode == 0) { Qg = g_q;  Kg = g_k;  Vg = g_v;  Og = g_am;  }
    else           { Qg = g_qm; Kg = g_km; Vg = g_vm; Og = g_amv; }

    const int L    = (mode == 0) ? 1024 : 128;
    const int tid  = threadIdx.x;
    const int lane = tid & 31;
    const int w    = tid >> 5;            // warp 0..3
    const int gid  = lane >> 2;
    const int tig  = lane & 3;
    const int h    = blockIdx.y;
    const int bat  = blockIdx.z;
    const int q0   = blockIdx.x * 64;

    // ---- load Q tile (scaled) into Ps as floats ----
#pragma unroll
    for (int i = 0; i < 8; i++) {
        int idx = tid + i * 128;
        int tkn = idx >> 4, d4 = idx & 15;
        int m = tok_idx(mode, bat, q0 + tkn);
        float4 qv = *(const float4*)(Qg + (size_t)m * DMODEL + h * DHEAD + d4 * 4);
        float4 s = make_float4(qv.x * 0.125f, qv.y * 0.125f, qv.z * 0.125f, qv.w * 0.125f);
        *(float4*)&Pf[tkn * AT_STR + d4 * 4] = s;
    }
    __syncthreads();

    // ---- build persistent Q A-fragments (8 k-steps x 4 regs) ----
    uint32_t qa[8][4];
    const int qr = w * 16 + gid;
#pragma unroll
    for (int ks = 0; ks < 8; ks++) {
        qa[ks][0] = to_tf32(Pf[qr * AT_STR + ks * 8 + tig]);
        qa[ks][1] = to_tf32(Pf[(qr + 8) * AT_STR + ks * 8 + tig]);
        qa[ks][2] = to_tf32(Pf[qr * AT_STR + ks * 8 + tig + 4]);
        qa[ks][3] = to_tf32(Pf[(qr + 8) * AT_STR + ks * 8 + tig + 4]);
    }

    float m0r = -1e30f, m1r = -1e30f, l0 = 0.f, l1 = 0.f;
    float o[8][4];
#pragma unroll
    for (int nt = 0; nt < 8; nt++)
#pragma unroll
        for (int i = 0; i < 4; i++) o[nt][i] = 0.f;

    for (int kt = 0; kt < L; kt += 64) {
        __syncthreads();   // prior-iter Vt reads (and iter-0 Q frag reads) done
        // ---- load K tile [tok][d] and V tile transposed [d][tok], tf32 ----
#pragma unroll
        for (int i = 0; i < 8; i++) {
            int idx = tid + i * 128;
            int tkn = idx >> 4, d4 = idx & 15;
            int m = tok_idx(mode, bat, kt + tkn);
            const float* kb = Kg + (size_t)m * DMODEL + h * DHEAD + d4 * 4;
            float4 kv = *(const float4*)kb;
            *(uint4*)&Ks[tkn * AT_STR + d4 * 4] =
                make_uint4(to_tf32(kv.x), to_tf32(kv.y), to_tf32(kv.z), to_tf32(kv.w));
            float4 vv = *(const float4*)(Vg + (size_t)m * DMODEL + h * DHEAD + d4 * 4);
            Vt[(d4 * 4 + 0) * AT_STR + tkn] = to_tf32(vv.x);
            Vt[(d4 * 4 + 1) * AT_STR + tkn] = to_tf32(vv.y);
            Vt[(d4 * 4 + 2) * AT_STR + tkn] = to_tf32(vv.z);
            Vt[(d4 * 4 + 3) * AT_STR + tkn] = to_tf32(vv.w);
        }
        __syncthreads();

        // ---- S = Q.K^T ----
        float s[8][4];
#pragma unroll
        for (int nt = 0; nt < 8; nt++)
#pragma unroll
            for (int i = 0; i < 4; i++) s[nt][i] = 0.f;
#pragma unroll
        for (int ks = 0; ks < 8; ks++) {
#pragma unroll
            for (int nt = 0; nt < 8; nt++) {
                uint32_t kb[2];
                kb[0] = Ks[(nt * 8 + gid) * AT_STR + ks * 8 + tig];
                kb[1] = Ks[(nt * 8 + gid) * AT_STR + ks * 8 + tig + 4];
                mma_tf32(s[nt], qa[ks], kb);
            }
        }

        // ---- online softmax (rows qr and qr+8) ----
        float tm0 = -1e30f, tm1 = -1e30f;
#pragma unroll
        for (int nt = 0; nt < 8; nt++) {
            tm0 = fmaxf(tm0, fmaxf(s[nt][0], s[nt][1]));
            tm1 = fmaxf(tm1, fmaxf(s[nt][2], s[nt][3]));
        }
        tm0 = fmaxf(tm0, __shfl_xor_sync(0xffffffffu, tm0, 1));
        tm0 = fmaxf(tm0, __shfl_xor_sync(0xffffffffu, tm0, 2));
        tm1 = fmaxf(tm1, __shfl_xor_sync(0xffffffffu, tm1, 1));
        tm1 = fmaxf(tm1, __shfl_xor_sync(0xffffffffu, tm1, 2));
        float mn0 = fmaxf(m0r, tm0), mn1 = fmaxf(m1r, tm1);
        float a0 = __expf(m0r - mn0), a1 = __expf(m1r - mn1);
        m0r = mn0; m1r = mn1;
        float ts0 = 0.f, ts1 = 0.f;
#pragma unroll
        for (int nt = 0; nt < 8; nt++) {
            s[nt][0] = __expf(s[nt][0] - mn0);
            s[nt][1] = __expf(s[nt][1] - mn0);
            s[nt][2] = __expf(s[nt][2] - mn1);
            s[nt][3] = __expf(s[nt][3] - mn1);
            ts0 += s[nt][0] + s[nt][1];
            ts1 += s[nt][2] + s[nt][3];
            o[nt][0] *= a0; o[nt][1] *= a0;
            o[nt][2] *= a1; o[nt][3] *= a1;
        }
        ts0 += __shfl_xor_sync(0xffffffffu, ts0, 1);
        ts0 += __shfl_xor_sync(0xffffffffu, ts0, 2);
        ts1 += __shfl_xor_sync(0xffffffffu, ts1, 1);
        ts1 += __shfl_xor_sync(0xffffffffu, ts1, 2);
        l0 = l0 * a0 + ts0;
        l1 = l1 * a1 + ts1;

        // ---- P -> warp-private smem (tf32), then PV MMA ----
        __syncwarp();
#pragma unroll
        for (int nt = 0; nt < 8; nt++) {
            *(uint2*)&Ps[qr * AT_STR + nt * 8 + 2 * tig] =
                make_uint2(to_tf32(s[nt][0]), to_tf32(s[nt][1]));
            *(uint2*)&Ps[(qr + 8) * AT_STR + nt * 8 + 2 * tig] =
                make_uint2(to_tf32(s[nt][2]), to_tf32(s[nt][3]));
        }
        __syncwarp();
#pragma unroll
        for (int ks = 0; ks < 8; ks++) {
            uint32_t pa[4];
            pa[0] = Ps[qr * AT_STR + ks * 8 + tig];
            pa[1] = Ps[(qr + 8) * AT_STR + ks * 8 + tig];
            pa[2] = Ps[qr * AT_STR + ks * 8 + tig + 4];
            pa[3] = Ps[(qr + 8) * AT_STR + ks * 8 + tig + 4];
#pragma unroll
            for (int nt = 0; nt < 8; nt++) {
                uint32_t vb[2];
                vb[0] = Vt[(nt * 8 + gid) * AT_STR + ks * 8 + tig];
                vb[1] = Vt[(nt * 8 + gid) * AT_STR + ks * 8 + tig + 4];
                mma_tf32(o[nt], pa, vb);
            }
        }
    }

    // ---- epilogue: normalize + view combination, float2 stores ----
    const float inv0 = 1.f / l0, inv1 = 1.f / l1;
    const int p0 = q0 + qr, p1 = p0 + 8;
    const int gm0 = tok_idx(mode, bat, p0);
    const int gm1 = tok_idx(mode, bat, p1);
    float w0 = 1.f, w1 = 1.f;
    bool rmw0 = false, rmw1 = false;
    if (mode == 1) {
        int v0 = p0 >> 5; w0 = (v0 == 0 || v0 == 2) ? 0.5f : 1.0f;
        int v1 = p1 >> 5; w1 = (v1 == 0 || v1 == 2) ? 0.5f : 1.0f;
    } else if (mode == 2) {
        rmw0 = (p0 >> 5) < 2;
        rmw1 = (p1 >> 5) < 2;
    }
#pragma unroll
    for (int nt = 0; nt < 8; nt++) {
        int col = h * DHEAD + nt * 8 + 2 * tig;
        float* op0 = Og + (size_t)gm0 * DMODEL + col;
        float* op1 = Og + (size_t)gm1 * DMODEL + col;
        float2 r0 = make_float2(o[nt][0] * inv0 * w0, o[nt][1] * inv0 * w0);
        float2 r1 = make_float2(o[nt][2] * inv1 * w1, o[nt][3] * inv1 * w1);
        if (rmw0) { float2 pv = *(float2*)op0; r0.x = pv.x + 0.5f * r0.x; r0.y = pv.y + 0.5f * r0.y; }
        if (rmw1) { float2 pv = *(float2*)op1; r1.x = pv.x + 0.5f * r1.x; r1.y = pv.y + 0.5f * r1.y; }
        *(float2*)op0 = r0;
        *(float2*)op1 = r1;
    }
}

// =====================================================================
extern "C" void kernel_launch(void* const* d_in, const int* in_sizes, int n_in,
                              void* d_out, int out_size)
{
    const float* x   = (const float*)d_in[0];
    const float* Wq  = (const float*)d_in[1];
    const float* Wk  = (const float*)d_in[2];
    const float* Wv  = (const float*)d_in[3];
    const float* Wo  = (const float*)d_in[4];
    const float* bo  = (const float*)d_in[5];
    const float* Wqm = (const float*)d_in[6];
    const float* Wkm = (const float*)d_in[7];
    const float* Wvm = (const float*)d_in[8];
    const float* Wom = (const float*)d_in[9];
    const float* bom = (const float*)d_in[10];
    float* out = (float*)d_out;

    cudaFuncSetAttribute(attn_tc, cudaFuncAttributeMaxDynamicSharedMemorySize,
                         AT_SMEM_BYTES);

    gemm_proj_tc<<<dim3(8, 96, 6), 256>>>(x, Wq, Wk, Wv, Wqm, Wkm, Wvm);

    attn_tc<<<dim3(16, 16, 12), 128, AT_SMEM_BYTES>>>(0);  // main
    attn_tc<<<dim3(2, 16, 64),  128, AT_SMEM_BYTES>>>(1);  // row MV
    attn_tc<<<dim3(2, 16, 64),  128, AT_SMEM_BYTES>>>(2);  // col MV

    gemm_out_tc<<<dim3(8, 96), 256>>>(Wo, bo, Wom, bom, x, out);
}